// round 6
// baseline (speedup 1.0000x reference)
#include <cuda_runtime.h>
#include <cstdint>
#include <math.h>

// ---------------- problem constants ----------------
constexpr int T_TOK  = 8192;    // B*S
constexpr int D_MODEL = 1024;
constexpr int N_EXP  = 8;
constexpr int DFF    = 4096;
constexpr int CAP    = 1280;    // ceil(1.25*8192/8)
constexpr float INV127 = 1.f / 127.f;
constexpr float INV256 = 1.f / 256.f;

// ---------------- scratch (__device__ globals; alloc-free rule) ----------------
__device__ float  g_prob[T_TOK];
__device__ int    g_expert[T_TOK];
__device__ int    g_pos[T_TOK];
__device__ int    g_cnt[N_EXP];
__device__ int    g_slot2tok[N_EXP * CAP];
__device__ float  g_slot_prob[N_EXP * CAP];
__device__ int    g_hmax [N_EXP * CAP];      // float bits, h rowmax (>=0)
__device__ int    g_w1max[N_EXP * DFF];      // float bits, |w1| colmax
__device__ int    g_w2max[N_EXP * D_MODEL];  // float bits, |w2| colmax
__device__ float  g_as[N_EXP * CAP];         // token row scale
__device__ float  g_hs[N_EXP * CAP];         // h row scale
__device__ __align__(16) int8_t g_aq1[(size_t)N_EXP*CAP*D_MODEL];
__device__ __align__(16) int8_t g_aq2[(size_t)N_EXP*CAP*D_MODEL];
__device__ __align__(16) int8_t g_w1q1[(size_t)N_EXP*DFF*D_MODEL];   // [e][dff][d] K-major
__device__ __align__(16) int8_t g_w1q2[(size_t)N_EXP*DFF*D_MODEL];
__device__ __align__(16) int8_t g_w2q1[(size_t)N_EXP*D_MODEL*DFF];   // [e][d][dff] K-major
__device__ __align__(16) int8_t g_w2q2[(size_t)N_EXP*D_MODEL*DFF];
__device__ __align__(16) int8_t g_hq1[(size_t)N_EXP*CAP*DFF];
__device__ __align__(16) int8_t g_hq2[(size_t)N_EXP*CAP*DFF];
__device__ float  g_h[(size_t)N_EXP*CAP*DFF];

// ---------------- helpers ----------------
static __device__ __forceinline__ uint32_t smem_u32(const void* p){
    uint32_t a;
    asm("{ .reg .u64 t; cvta.to.shared.u64 t, %1; cvt.u32.u64 %0, t; }" : "=r"(a) : "l"(p));
    return a;
}
static __device__ __forceinline__ void cp_async16(uint32_t s, const void* g){
    asm volatile("cp.async.cg.shared.global [%0], [%1], 16;" :: "r"(s), "l"(g) : "memory");
}
static __device__ __forceinline__ void cp_commit(){
    asm volatile("cp.async.commit_group;" ::: "memory");
}
template<int N>
static __device__ __forceinline__ void cp_wait(){
    asm volatile("cp.async.wait_group %0;" :: "n"(N) : "memory");
}
static __device__ __forceinline__ void ldmx4(uint32_t* r, uint32_t addr){
    asm volatile("ldmatrix.sync.aligned.m8n8.x4.shared.b16 {%0,%1,%2,%3}, [%4];"
                 : "=r"(r[0]), "=r"(r[1]), "=r"(r[2]), "=r"(r[3]) : "r"(addr));
}
static __device__ __forceinline__ void ldmx2(uint32_t* r, uint32_t addr){
    asm volatile("ldmatrix.sync.aligned.m8n8.x2.shared.b16 {%0,%1}, [%2];"
                 : "=r"(r[0]), "=r"(r[1]) : "r"(addr));
}
// int8 IMMA: 16x8x32, s32 accumulate
static __device__ __forceinline__ void imma(int* c, const uint32_t* a, const uint32_t* b){
    asm volatile(
        "mma.sync.aligned.m16n8k32.row.col.s32.s8.s8.s32 "
        "{%0,%1,%2,%3}, {%4,%5,%6,%7}, {%8,%9}, {%0,%1,%2,%3};"
        : "+r"(c[0]), "+r"(c[1]), "+r"(c[2]), "+r"(c[3])
        : "r"(a[0]), "r"(a[1]), "r"(a[2]), "r"(a[3]), "r"(b[0]), "r"(b[1]));
}
static __device__ __forceinline__ int clamp127(int q){
    return q > 127 ? 127 : (q < -127 ? -127 : q);
}
// quantize float4 -> 4x(q1,q2) packed as two u32 (byte lanes)
static __device__ __forceinline__ void quant4(float4 v, float sq, float inv,
                                              uint32_t &w1, uint32_t &w2){
    int a0 = __float2int_rn(v.x * inv);
    int a1 = __float2int_rn(v.y * inv);
    int a2 = __float2int_rn(v.z * inv);
    int a3 = __float2int_rn(v.w * inv);
    int b0 = clamp127(__float2int_rn((v.x - sq * (float)a0) * inv * 256.f));
    int b1 = clamp127(__float2int_rn((v.y - sq * (float)a1) * inv * 256.f));
    int b2 = clamp127(__float2int_rn((v.z - sq * (float)a2) * inv * 256.f));
    int b3 = clamp127(__float2int_rn((v.w - sq * (float)a3) * inv * 256.f));
    w1 = (a0 & 255) | ((a1 & 255) << 8) | ((a2 & 255) << 16) | ((a3 & 255) << 24);
    w2 = (b0 & 255) | ((b1 & 255) << 8) | ((b2 & 255) << 16) | ((b3 & 255) << 24);
}

// ---------------- 1) gate: fp64-accum logits, softmax top-1 ----------------
__global__ void moe_gate(const float* __restrict__ tokens, const float* __restrict__ gw){
    __shared__ float s_gw[N_EXP * D_MODEL];  // 32 KB
    for (int i = threadIdx.x; i < N_EXP * D_MODEL; i += blockDim.x) s_gw[i] = gw[i];
    __syncthreads();
    int lane  = threadIdx.x & 31;
    int warp  = (blockIdx.x * blockDim.x + threadIdx.x) >> 5;
    int nwarp = (gridDim.x * blockDim.x) >> 5;
    for (int t = warp; t < T_TOK; t += nwarp){
        const float* tok = tokens + (size_t)t * D_MODEL;
        double acc[N_EXP];
        #pragma unroll
        for (int e = 0; e < N_EXP; e++) acc[e] = 0.0;
        for (int d = lane; d < D_MODEL; d += 32){
            double x = (double)tok[d];
            #pragma unroll
            for (int e = 0; e < N_EXP; e++) acc[e] += x * (double)s_gw[e * D_MODEL + d];
        }
        #pragma unroll
        for (int e = 0; e < N_EXP; e++){
            #pragma unroll
            for (int o = 16; o > 0; o >>= 1)
                acc[e] += __shfl_down_sync(0xffffffffu, acc[e], o);
        }
        if (lane == 0){
            int best = 0; double bv = acc[0];
            #pragma unroll
            for (int e = 1; e < N_EXP; e++) if (acc[e] > bv){ bv = acc[e]; best = e; }
            double s = 0.0;
            #pragma unroll
            for (int e = 0; e < N_EXP; e++) s += exp(acc[e] - bv);
            g_prob[t]   = (float)(1.0 / s);
            g_expert[t] = best;
        }
    }
}

// ---------------- 2) order-preserving per-expert rank scan (capacity) ----------------
__global__ void moe_scan(){
    __shared__ int s_base[N_EXP];
    __shared__ int s_wcnt[N_EXP][32];
    int tid = threadIdx.x, lane = tid & 31, w = tid >> 5;
    if (tid < N_EXP) s_base[tid] = 0;
    for (int chunk = 0; chunk < T_TOK / 1024; chunk++){
        if (tid < N_EXP * 32) ((int*)s_wcnt)[tid] = 0;
        __syncthreads();
        int t = chunk * 1024 + tid;
        int e = g_expert[t];
        unsigned m = __match_any_sync(0xffffffffu, e);
        int rw = __popc(m & ((1u << lane) - 1u));
        if (rw == 0) s_wcnt[e][w] = __popc(m);
        __syncthreads();
        int base = s_base[e];
        for (int ww = 0; ww < w; ww++) base += s_wcnt[e][ww];
        int rank = base + rw;
        g_pos[t] = (rank < CAP) ? rank : -1;
        __syncthreads();
        if (tid < N_EXP){
            int s = 0;
            #pragma unroll
            for (int ww = 0; ww < 32; ww++) s += s_wcnt[tid][ww];
            s_base[tid] += s;
        }
        __syncthreads();
    }
    if (tid < N_EXP) g_cnt[tid] = (s_base[tid] < CAP) ? s_base[tid] : CAP;
}

// ---------------- 2b) per-launch state reset ----------------
__global__ void moe_init(){
    int i = blockIdx.x * blockDim.x + threadIdx.x;
    if (i < N_EXP * CAP){ g_slot2tok[i] = -1; g_hmax[i] = 0; }
    if (i < N_EXP * DFF)      g_w1max[i] = 0;
    if (i < N_EXP * D_MODEL)  g_w2max[i] = 0;
}

// ---------------- 3) gather tokens -> int8 2-digit dispatch + slot maps ----------------
__global__ void moe_gather(const float* __restrict__ tokens){
    int t = blockIdx.x;
    int pos = g_pos[t];
    if (pos < 0) return;
    int e = g_expert[t];
    int tid = threadIdx.x, lane = tid & 31, w = tid >> 5;   // 128 threads
    __shared__ float s_max[4];

    const float4* src = (const float4*)(tokens + (size_t)t * D_MODEL);
    float4 v0 = src[tid];
    float4 v1 = src[tid + 128];
    float m = fmaxf(fmaxf(fmaxf(fabsf(v0.x), fabsf(v0.y)), fmaxf(fabsf(v0.z), fabsf(v0.w))),
                    fmaxf(fmaxf(fabsf(v1.x), fabsf(v1.y)), fmaxf(fabsf(v1.z), fabsf(v1.w))));
    #pragma unroll
    for (int o = 16; o > 0; o >>= 1) m = fmaxf(m, __shfl_xor_sync(0xffffffffu, m, o));
    if (lane == 0) s_max[w] = m;
    __syncthreads();
    m = fmaxf(fmaxf(s_max[0], s_max[1]), fmaxf(s_max[2], s_max[3]));

    float sq  = m * INV127;
    float inv = (m > 0.f) ? 127.f / m : 0.f;
    size_t dst = ((size_t)e * CAP + pos) * D_MODEL;
    uint32_t q1, q2;
    quant4(v0, sq, inv, q1, q2);
    *(uint32_t*)(g_aq1 + dst + 4 * tid) = q1;
    *(uint32_t*)(g_aq2 + dst + 4 * tid) = q2;
    quant4(v1, sq, inv, q1, q2);
    *(uint32_t*)(g_aq1 + dst + 4 * (tid + 128)) = q1;
    *(uint32_t*)(g_aq2 + dst + 4 * (tid + 128)) = q2;

    if (tid == 0){
        g_slot2tok[e * CAP + pos]  = t;
        g_slot_prob[e * CAP + pos] = g_prob[t];
        g_as[e * CAP + pos]        = sq;
    }
}

// ---------------- 4a) weight colmax (|w| max over K per output column) ----------------
template<bool W1>
__global__ void moe_colmax(const float* __restrict__ w){
    constexpr int R = W1 ? D_MODEL : DFF;
    constexpr int C = W1 ? DFF : D_MODEL;
    int* gmax = W1 ? g_w1max : g_w2max;
    int e = blockIdx.y;
    int c = blockIdx.x * 256 + threadIdx.x;
    int r0 = blockIdx.z * (R / 8);
    const float* wp = w + (size_t)e * R * C + c;
    float m = 0.f;
    for (int r = r0; r < r0 + R / 8; r++)
        m = fmaxf(m, fabsf(wp[(size_t)r * C]));
    atomicMax(&gmax[e * C + c], __float_as_int(m));
}

// ---------------- 4b) weight transpose + int8 2-digit quantize (K-major) ----------------
template<bool W1>
__global__ void moe_tw(const float* __restrict__ w){
    constexpr int R = W1 ? D_MODEL : DFF;   // rows of w  (= K of gemm)
    constexpr int C = W1 ? DFF : D_MODEL;   // cols of w  (= N of gemm)
    int8_t* oq1 = W1 ? g_w1q1 : g_w2q1;
    int8_t* oq2 = W1 ? g_w1q2 : g_w2q2;
    const int* gmax = W1 ? g_w1max : g_w2max;
    __shared__ float tile[32][33];
    int e = blockIdx.z;
    int c0 = blockIdx.x * 32, r0 = blockIdx.y * 32;
    const float* wp = w + (size_t)e * R * C;
    int x = threadIdx.x, y0 = threadIdx.y;    // blockDim (32, 8)
    #pragma unroll
    for (int yy = 0; yy < 32; yy += 8)
        tile[y0 + yy][x] = wp[(size_t)(r0 + y0 + yy) * C + c0 + x];
    __syncthreads();
    int8_t* p1 = oq1 + (size_t)e * R * C;
    int8_t* p2 = oq2 + (size_t)e * R * C;
    #pragma unroll
    for (int yy = 0; yy < 32; yy += 8){
        int c = c0 + y0 + yy;
        float mx  = __int_as_float(gmax[e * C + c]);
        float sq  = mx * INV127;
        float inv = (mx > 0.f) ? 127.f / mx : 0.f;
        float v = tile[x][y0 + yy];
        int q1 = __float2int_rn(v * inv);
        int q2 = clamp127(__float2int_rn((v - sq * (float)q1) * inv * 256.f));
        size_t o = (size_t)c * R + r0 + x;
        p1[o] = (int8_t)q1; p2[o] = (int8_t)q2;
    }
}

// ---------------- 5) IMMA int8x2 GEMM: BM=128 BN=128 BK=64(s8), 3-stage cp.async ----------
constexpr int BM = 128, BN = 128, BK = 64;
constexpr int ROW_B   = 80;                      // 64B payload + 16B pad
constexpr int OFF_A1  = 0;
constexpr int OFF_A2  = 128 * ROW_B;
constexpr int OFF_B1  = 256 * ROW_B;
constexpr int OFF_B2  = 384 * ROW_B;
constexpr int STAGE_B = 512 * ROW_B;             // 40960
constexpr int NSTAGE  = 3;
constexpr int GEMM_SMEM = NSTAGE * STAGE_B;      // 122880

template<bool G1>
__global__ void __launch_bounds__(256, 1) moe_gemm(const float* __restrict__ bias,
                                                   float* __restrict__ out){
    constexpr int KTOT = G1 ? D_MODEL : DFF;
    constexpr int NTOT = G1 ? DFF : D_MODEL;
    const int8_t* Aq1 = G1 ? g_aq1  : g_hq1;
    const int8_t* Aq2 = G1 ? g_aq2  : g_hq2;
    const int8_t* Bq1 = G1 ? g_w1q1 : g_w2q1;
    const int8_t* Bq2 = G1 ? g_w1q2 : g_w2q2;

    int e = blockIdx.z, m0 = blockIdx.y * BM, n0 = blockIdx.x * BN;
    int cnt = g_cnt[e];
    if (m0 >= cnt) return;

    extern __shared__ char smem[];
    uint32_t sb = smem_u32(smem);

    int tid  = threadIdx.x;
    int lane = tid & 31;
    int wid  = tid >> 5;
    int warpM = wid & 1;            // 2 x 4 warp grid; warp tile 64x32
    int warpN = wid >> 1;

    const int8_t* baseA1 = Aq1 + ((size_t)e * CAP  + m0) * KTOT;
    const int8_t* baseA2 = Aq2 + ((size_t)e * CAP  + m0) * KTOT;
    const int8_t* baseB1 = Bq1 + ((size_t)e * NTOT + n0) * KTOT;
    const int8_t* baseB2 = Bq2 + ((size_t)e * NTOT + n0) * KTOT;

    // per-thread cp.async slots: idx = tid + i*256 (i<8); row = idx>>2 (0..511), ch = idx&3
    const int8_t* gptr[8];
    uint32_t sptr[8];
    #pragma unroll
    for (int i = 0; i < 8; i++){
        int idx = tid + i * 256;
        int row = idx >> 2, ch = idx & 3;
        const int8_t* gb; uint32_t so;
        if (row < 128)      { gb = baseA1 + (size_t)row * KTOT;        so = OFF_A1 + row * ROW_B; }
        else if (row < 256) { gb = baseA2 + (size_t)(row-128) * KTOT;  so = OFF_A2 + (row-128) * ROW_B; }
        else if (row < 384) { gb = baseB1 + (size_t)(row-256) * KTOT;  so = OFF_B1 + (row-256) * ROW_B; }
        else                { gb = baseB2 + (size_t)(row-384) * KTOT;  so = OFF_B2 + (row-384) * ROW_B; }
        gptr[i] = gb + ch * 16;
        sptr[i] = sb + so + ch * 16;
    }
    auto load_stage = [&](int kc, int stage){
        size_t koff = (size_t)kc * BK;
        uint32_t soff = stage * STAGE_B;
        #pragma unroll
        for (int i = 0; i < 8; i++)
            cp_async16(sptr[i] + soff, gptr[i] + koff);
    };

    constexpr int NK = KTOT / BK;
    load_stage(0, 0); cp_commit();
    load_stage(1, 1); cp_commit();

    int acc1[4][4][4], acc2[4][4][4];
    #pragma unroll
    for (int mt = 0; mt < 4; mt++)
        #pragma unroll
        for (int nt = 0; nt < 4; nt++)
            #pragma unroll
            for (int c = 0; c < 4; c++){ acc1[mt][nt][c] = 0; acc2[mt][nt][c] = 0; }

    uint32_t aoff = (uint32_t)((warpM * 64 + (lane & 7) + ((lane >> 3) & 1) * 8) * ROW_B
                    + ((lane >> 4) & 1) * 16);
    uint32_t boff = (uint32_t)((warpN * 32 + (lane & 7)) * ROW_B + ((lane >> 3) & 1) * 16);

    int cur = 0, lds = 2;
    #pragma unroll 1
    for (int kc = 0; kc < NK; kc++){
        cp_wait<NSTAGE - 2>();
        __syncthreads();
        int nx = kc + NSTAGE - 1;
        if (nx < NK) load_stage(nx, lds);
        cp_commit();

        uint32_t st = sb + cur * STAGE_B;
        uint32_t a1 = st + OFF_A1 + aoff, a2 = st + OFF_A2 + aoff;
        uint32_t b1 = st + OFF_B1 + boff, b2 = st + OFF_B2 + boff;
        #pragma unroll
        for (int ks = 0; ks < 2; ks++){          // two k32 steps per 64B chunk
            uint32_t bq1[4][2], bq2[4][2];
            #pragma unroll
            for (int nt = 0; nt < 4; nt++){
                ldmx2(bq1[nt], b1 + nt * 8 * ROW_B + ks * 32);
                ldmx2(bq2[nt], b2 + nt * 8 * ROW_B + ks * 32);
            }
            #pragma unroll
            for (int mt = 0; mt < 4; mt++){
                uint32_t aq1[4], aq2[4];
                ldmx4(aq1, a1 + mt * 16 * ROW_B + ks * 32);
                ldmx4(aq2, a2 + mt * 16 * ROW_B + ks * 32);
                #pragma unroll
                for (int nt = 0; nt < 4; nt++)
                    imma(acc1[mt][nt], aq1, bq1[nt]);      // q1*p1
                #pragma unroll
                for (int nt = 0; nt < 4; nt++)
                    imma(acc2[mt][nt], aq1, bq2[nt]);      // q1*p2
                #pragma unroll
                for (int nt = 0; nt < 4; nt++)
                    imma(acc2[mt][nt], aq2, bq1[nt]);      // q2*p1 (same scale level)
            }
        }
        cur = (cur == NSTAGE - 1) ? 0 : cur + 1;
        lds = (lds == NSTAGE - 1) ? 0 : lds + 1;
    }

    // epilogue: val = sA*sB*(acc1 + acc2/256) + bias
    int rloc  = warpM * 64 + (lane >> 2);
    int cbase = n0 + warpN * 32 + 2 * (lane & 3);
    const float* bptr = bias + (size_t)e * NTOT;
    const int* bmax = G1 ? g_w1max : g_w2max;
    #pragma unroll
    for (int mt = 0; mt < 4; mt++){
        #pragma unroll
        for (int h = 0; h < 2; h++){
            int slot = m0 + rloc + mt * 16 + h * 8;
            size_t row = (size_t)e * CAP + slot;
            float sA;
            int t = 0; float p = 0.f; float* op = nullptr;
            if constexpr (G1){
                sA = g_as[row];
            } else {
                t = g_slot2tok[row];
                if (t < 0) continue;
                sA = g_hs[row];
                p = g_slot_prob[row];
                op = out + (size_t)t * D_MODEL;
            }
            float rmax = 0.f;
            #pragma unroll
            for (int nt = 0; nt < 4; nt++){
                int n = cbase + nt * 8;
                float sB0 = __int_as_float(bmax[e * NTOT + n])     * INV127;
                float sB1 = __int_as_float(bmax[e * NTOT + n + 1]) * INV127;
                float v0 = sA * sB0 * ((float)acc1[mt][nt][h*2+0] + (float)acc2[mt][nt][h*2+0] * INV256)
                         + __ldg(bptr + n);
                float v1 = sA * sB1 * ((float)acc1[mt][nt][h*2+1] + (float)acc2[mt][nt][h*2+1] * INV256)
                         + __ldg(bptr + n + 1);
                if constexpr (G1){
                    v0 = fmaxf(v0, 0.f); v1 = fmaxf(v1, 0.f);
                    *(float2*)(g_h + row * DFF + n) = make_float2(v0, v1);
                    rmax = fmaxf(rmax, fmaxf(v0, v1));
                } else {
                    *(float2*)(op + n) = make_float2(v0 * p, v1 * p);
                }
            }
            if constexpr (G1){
                rmax = fmaxf(rmax, __shfl_xor_sync(0xffffffffu, rmax, 1));
                rmax = fmaxf(rmax, __shfl_xor_sync(0xffffffffu, rmax, 2));
                if ((lane & 3) == 0) atomicMax(&g_hmax[row], __float_as_int(rmax));
            }
        }
    }
}

// ---------------- 5b) quantize h rows to int8 x2 ----------------
__global__ void moe_hq(){
    int row = blockIdx.x;                       // 0 .. N_EXP*CAP-1
    float m = __int_as_float(g_hmax[row]);
    float sq  = m * INV127;
    float inv = (m > 0.f) ? 127.f / m : 0.f;
    if (threadIdx.x == 0) g_hs[row] = sq;
    const float4* src = (const float4*)(g_h + (size_t)row * DFF);
    size_t dst = (size_t)row * DFF;
    for (int i = threadIdx.x; i < DFF / 4; i += blockDim.x){
        float4 v = src[i];
        uint32_t q1, q2;
        quant4(v, sq, inv, q1, q2);
        *(uint32_t*)(g_hq1 + dst + 4 * i) = q1;
        *(uint32_t*)(g_hq2 + dst + 4 * i) = q2;
    }
}

// ---------------- 6) zero-fill dropped tokens ----------------
__global__ void moe_zero_dropped(float* __restrict__ out){
    int t = blockIdx.x;
    if (g_pos[t] >= 0) return;
    float4* o = (float4*)(out + (size_t)t * D_MODEL);
    for (int i = threadIdx.x; i < D_MODEL / 4; i += blockDim.x)
        o[i] = make_float4(0.f, 0.f, 0.f, 0.f);
}

// ---------------- launch ----------------
extern "C" void kernel_launch(void* const* d_in, const int* in_sizes, int n_in,
                              void* d_out, int out_size){
    const float* inputs = (const float*)d_in[0];
    const float* gate_w = (const float*)d_in[1];
    const float* w1     = (const float*)d_in[2];
    const float* b1     = (const float*)d_in[3];
    const float* w2     = (const float*)d_in[4];
    const float* b2     = (const float*)d_in[5];
    float* out = (float*)d_out;

    cudaFuncSetAttribute(moe_gemm<true>,  cudaFuncAttributeMaxDynamicSharedMemorySize, GEMM_SMEM);
    cudaFuncSetAttribute(moe_gemm<false>, cudaFuncAttributeMaxDynamicSharedMemorySize, GEMM_SMEM);

    moe_gate<<<128, 256>>>(inputs, gate_w);
    moe_scan<<<1, 1024>>>();
    moe_init<<<(N_EXP * DFF + 255) / 256, 256>>>();
    moe_gather<<<T_TOK, 128>>>(inputs);
    moe_colmax<true ><<<dim3(DFF / 256,     N_EXP, 8), 256>>>(w1);
    moe_colmax<false><<<dim3(D_MODEL / 256, N_EXP, 8), 256>>>(w2);
    moe_tw<true ><<<dim3(DFF / 32,     D_MODEL / 32, N_EXP), dim3(32, 8)>>>(w1);
    moe_tw<false><<<dim3(D_MODEL / 32, DFF / 32,     N_EXP), dim3(32, 8)>>>(w2);
    moe_gemm<true ><<<dim3(DFF / BN,     CAP / BM, N_EXP), 256, GEMM_SMEM>>>(b1, nullptr);
    moe_hq<<<N_EXP * CAP, 256>>>();
    moe_gemm<false><<<dim3(D_MODEL / BN, CAP / BM, N_EXP), 256, GEMM_SMEM>>>(b2, out);
    moe_zero_dropped<<<T_TOK, 128>>>(out);
}

// round 7
// speedup vs baseline: 2.5106x; 2.5106x over previous
#include <cuda_runtime.h>
#include <cuda_fp16.h>
#include <cstdint>
#include <math.h>

// ---------------- problem constants ----------------
constexpr int T_TOK  = 8192;    // B*S
constexpr int D_MODEL = 1024;
constexpr int N_EXP  = 8;
constexpr int DFF    = 4096;
constexpr int CAP    = 1280;    // ceil(1.25*8192/8)
constexpr float LO_SCALE   = 2048.f;       // lo = (x - hi(x)) * 2^11
constexpr float INV_LO     = 1.f / 2048.f;

// ---------------- scratch (__device__ globals; alloc-free rule) ----------------
__device__ float  g_prob[T_TOK];
__device__ int    g_expert[T_TOK];
__device__ int    g_pos[T_TOK];
__device__ int    g_cnt[N_EXP];
__device__ int    g_slot2tok[N_EXP * CAP];
__device__ float  g_slot_prob[N_EXP * CAP];
__device__ __half g_disp_hi[(size_t)N_EXP*CAP*D_MODEL];
__device__ __half g_disp_lo[(size_t)N_EXP*CAP*D_MODEL];
__device__ __half g_w1_hi[(size_t)N_EXP*DFF*D_MODEL];   // [e][dff][d]  K-major
__device__ __half g_w2_hi[(size_t)N_EXP*D_MODEL*DFF];   // [e][d][dff]  K-major
__device__ __half g_h_hi[(size_t)N_EXP*CAP*DFF];
__device__ __half g_h_lo[(size_t)N_EXP*CAP*DFF];

// ---------------- helpers ----------------
static __device__ __forceinline__ uint32_t smem_u32(const void* p){
    uint32_t a;
    asm("{ .reg .u64 t; cvta.to.shared.u64 t, %1; cvt.u32.u64 %0, t; }" : "=r"(a) : "l"(p));
    return a;
}
static __device__ __forceinline__ void cp_async16(uint32_t s, const void* g){
    asm volatile("cp.async.cg.shared.global [%0], [%1], 16;" :: "r"(s), "l"(g) : "memory");
}
static __device__ __forceinline__ void cp_commit(){
    asm volatile("cp.async.commit_group;" ::: "memory");
}
template<int N>
static __device__ __forceinline__ void cp_wait(){
    asm volatile("cp.async.wait_group %0;" :: "n"(N) : "memory");
}
static __device__ __forceinline__ void ldmx4(uint32_t* r, uint32_t addr){
    asm volatile("ldmatrix.sync.aligned.m8n8.x4.shared.b16 {%0,%1,%2,%3}, [%4];"
                 : "=r"(r[0]), "=r"(r[1]), "=r"(r[2]), "=r"(r[3]) : "r"(addr));
}
static __device__ __forceinline__ void ldmx2(uint32_t* r, uint32_t addr){
    asm volatile("ldmatrix.sync.aligned.m8n8.x2.shared.b16 {%0,%1}, [%2];"
                 : "=r"(r[0]), "=r"(r[1]) : "r"(addr));
}
// fp16 operands, fp32 accumulator (main term)
static __device__ __forceinline__ void mma_f32(float* c, const uint32_t* a, const uint32_t* b){
    asm volatile(
        "mma.sync.aligned.m16n8k16.row.col.f32.f16.f16.f32 "
        "{%0,%1,%2,%3}, {%4,%5,%6,%7}, {%8,%9}, {%0,%1,%2,%3};"
        : "+f"(c[0]), "+f"(c[1]), "+f"(c[2]), "+f"(c[3])
        : "r"(a[0]), "r"(a[1]), "r"(a[2]), "r"(a[3]), "r"(b[0]), "r"(b[1]));
}
// fp16 operands, fp16 accumulator (correction term)
static __device__ __forceinline__ void mma_f16(uint32_t* c, const uint32_t* a, const uint32_t* b){
    asm volatile(
        "mma.sync.aligned.m16n8k16.row.col.f16.f16.f16.f16 "
        "{%0,%1}, {%2,%3,%4,%5}, {%6,%7}, {%0,%1};"
        : "+r"(c[0]), "+r"(c[1])
        : "r"(a[0]), "r"(a[1]), "r"(a[2]), "r"(a[3]), "r"(b[0]), "r"(b[1]));
}
// split fp32 -> fp16 hi + fp16 lo (lo = (x - hi)*2048, kept in normal range)
static __device__ __forceinline__ void split2(float a, float b, unsigned &hi, unsigned &lo){
    __half ha = __float2half_rn(a), hb = __float2half_rn(b);
    __half la = __float2half_rn((a - __half2float(ha)) * LO_SCALE);
    __half lb = __float2half_rn((b - __half2float(hb)) * LO_SCALE);
    __half2 H = __halves2half2(ha, hb);
    __half2 L = __halves2half2(la, lb);
    hi = *reinterpret_cast<unsigned*>(&H);
    lo = *reinterpret_cast<unsigned*>(&L);
}

// ---------------- 1) gate: fp64-accum logits, softmax top-1 ----------------
__global__ void moe_gate(const float* __restrict__ tokens, const float* __restrict__ gw){
    __shared__ float s_gw[N_EXP * D_MODEL];  // 32 KB
    for (int i = threadIdx.x; i < N_EXP * D_MODEL; i += blockDim.x) s_gw[i] = gw[i];
    __syncthreads();
    int lane  = threadIdx.x & 31;
    int warp  = (blockIdx.x * blockDim.x + threadIdx.x) >> 5;
    int nwarp = (gridDim.x * blockDim.x) >> 5;
    for (int t = warp; t < T_TOK; t += nwarp){
        const float* tok = tokens + (size_t)t * D_MODEL;
        double acc[N_EXP];
        #pragma unroll
        for (int e = 0; e < N_EXP; e++) acc[e] = 0.0;
        for (int d = lane; d < D_MODEL; d += 32){
            double x = (double)tok[d];
            #pragma unroll
            for (int e = 0; e < N_EXP; e++) acc[e] += x * (double)s_gw[e * D_MODEL + d];
        }
        #pragma unroll
        for (int e = 0; e < N_EXP; e++){
            #pragma unroll
            for (int o = 16; o > 0; o >>= 1)
                acc[e] += __shfl_down_sync(0xffffffffu, acc[e], o);
        }
        if (lane == 0){
            int best = 0; double bv = acc[0];
            #pragma unroll
            for (int e = 1; e < N_EXP; e++) if (acc[e] > bv){ bv = acc[e]; best = e; }
            double s = 0.0;
            #pragma unroll
            for (int e = 0; e < N_EXP; e++) s += exp(acc[e] - bv);
            g_prob[t]   = (float)(1.0 / s);
            g_expert[t] = best;
        }
    }
}

// ---------------- 2) order-preserving per-expert rank scan (capacity) ----------------
__global__ void moe_scan(){
    __shared__ int s_base[N_EXP];
    __shared__ int s_wcnt[N_EXP][32];
    int tid = threadIdx.x, lane = tid & 31, w = tid >> 5;
    if (tid < N_EXP) s_base[tid] = 0;
    for (int chunk = 0; chunk < T_TOK / 1024; chunk++){
        if (tid < N_EXP * 32) ((int*)s_wcnt)[tid] = 0;
        __syncthreads();
        int t = chunk * 1024 + tid;
        int e = g_expert[t];
        unsigned m = __match_any_sync(0xffffffffu, e);
        int rw = __popc(m & ((1u << lane) - 1u));
        if (rw == 0) s_wcnt[e][w] = __popc(m);
        __syncthreads();
        int base = s_base[e];
        for (int ww = 0; ww < w; ww++) base += s_wcnt[e][ww];
        int rank = base + rw;
        g_pos[t] = (rank < CAP) ? rank : -1;
        __syncthreads();
        if (tid < N_EXP){
            int s = 0;
            #pragma unroll
            for (int ww = 0; ww < 32; ww++) s += s_wcnt[tid][ww];
            s_base[tid] += s;
        }
        __syncthreads();
    }
    if (tid < N_EXP) g_cnt[tid] = (s_base[tid] < CAP) ? s_base[tid] : CAP;
}

// ---------------- 2b) slot map init ----------------
__global__ void moe_slot_init(){
    int i = blockIdx.x * blockDim.x + threadIdx.x;
    if (i < N_EXP * CAP) g_slot2tok[i] = -1;
}

// ---------------- 3) gather tokens -> dispatch (fp16 hi/lo) + slot maps ----------------
__global__ void moe_gather(const float* __restrict__ tokens){
    int t = blockIdx.x;
    int pos = g_pos[t];
    if (pos < 0) return;
    int e = g_expert[t];
    if (threadIdx.x == 0){
        g_slot2tok[e * CAP + pos]  = t;
        g_slot_prob[e * CAP + pos] = g_prob[t];
    }
    size_t dst = ((size_t)e * CAP + pos) * D_MODEL;
    const float4* src = (const float4*)(tokens + (size_t)t * D_MODEL);
    uint2* dh = (uint2*)(g_disp_hi + dst);
    uint2* dl = (uint2*)(g_disp_lo + dst);
    for (int i = threadIdx.x; i < D_MODEL / 4; i += blockDim.x){
        float4 v = src[i];
        uint2 H, L;
        split2(v.x, v.y, H.x, L.x);
        split2(v.z, v.w, H.y, L.y);
        dh[i] = H; dl[i] = L;
    }
}

// ---------------- 4) weight transpose (to K-major fp16, hi only) ----------------
template<bool W1>
__global__ void moe_tw(const float* __restrict__ w){
    constexpr int R = W1 ? D_MODEL : DFF;   // rows of w  (= K of gemm)
    constexpr int C = W1 ? DFF : D_MODEL;   // cols of w  (= N of gemm)
    __half* oh = W1 ? g_w1_hi : g_w2_hi;
    __shared__ float tile[32][33];
    int e = blockIdx.z;
    int c0 = blockIdx.x * 32, r0 = blockIdx.y * 32;
    const float* wp = w + (size_t)e * R * C;
    int x = threadIdx.x, y0 = threadIdx.y;    // blockDim (32, 8)
    #pragma unroll
    for (int yy = 0; yy < 32; yy += 8)
        tile[y0 + yy][x] = wp[(size_t)(r0 + y0 + yy) * C + c0 + x];
    __syncthreads();
    __half* poh = oh + (size_t)e * R * C;
    #pragma unroll
    for (int yy = 0; yy < 32; yy += 8){
        float v = tile[x][y0 + yy];
        size_t o = (size_t)(c0 + y0 + yy) * R + r0 + x;
        poh[o] = __float2half_rn(v);
    }
}

// ---------------- 5) HMMA fp16x2 GEMM: BM=128 BN=128 BK=32, 3-stage cp.async ----------------
// main term AhBh f32-accum; correction AlBh f16-accum (lo scaled by 2^11)
constexpr int BM = 128, BN = 128, BK = 32;
constexpr int ROW_B   = 80;                      // padded row stride (64B data + 16B pad)
constexpr int OFF_AH  = 0;
constexpr int OFF_AL  = 128 * ROW_B;
constexpr int OFF_BH  = 256 * ROW_B;
constexpr int STAGE_B = 384 * ROW_B;             // 30720
constexpr int NSTAGE  = 3;
constexpr int GEMM_SMEM = NSTAGE * STAGE_B;      // 92160

template<bool G1>
__global__ void __launch_bounds__(256, 1) moe_gemm(const float* __restrict__ bias,
                                                   float* __restrict__ out){
    constexpr int KTOT = G1 ? D_MODEL : DFF;
    constexpr int NTOT = G1 ? DFF : D_MODEL;
    const __half* Ahi = G1 ? g_disp_hi : g_h_hi;
    const __half* Alo = G1 ? g_disp_lo : g_h_lo;
    const __half* Bhi = G1 ? g_w1_hi : g_w2_hi;

    int e = blockIdx.z, m0 = blockIdx.y * BM, n0 = blockIdx.x * BN;
    int cnt = g_cnt[e];
    if (m0 >= cnt) return;          // expert has no tokens in this m-tile

    extern __shared__ char smem[];
    uint32_t sb = smem_u32(smem);

    int tid  = threadIdx.x;
    int lane = tid & 31;
    int wid  = tid >> 5;
    int warpM = wid & 1;            // 2 x 4 warp grid; warp tile 64x32
    int warpN = wid >> 1;

    const __half* baseAh = Ahi + ((size_t)e * CAP  + m0) * KTOT;
    const __half* baseAl = Alo + ((size_t)e * CAP  + m0) * KTOT;
    const __half* baseBh = Bhi + ((size_t)e * NTOT + n0) * KTOT;

    // per-thread cp.async slots: idx = tid + i*256 (i<6); row = idx>>2 (0..383), ch = idx&3
    const __half* gptr[6];
    uint32_t sptr[6];
    #pragma unroll
    for (int i = 0; i < 6; i++){
        int idx = tid + i * 256;
        int row = idx >> 2, ch = idx & 3;
        const __half* gb; uint32_t so;
        if (row < 128)      { gb = baseAh + (size_t)row * KTOT;        so = OFF_AH + row * ROW_B; }
        else if (row < 256) { gb = baseAl + (size_t)(row-128) * KTOT;  so = OFF_AL + (row-128) * ROW_B; }
        else                { gb = baseBh + (size_t)(row-256) * KTOT;  so = OFF_BH + (row-256) * ROW_B; }
        gptr[i] = gb + ch * 8;
        sptr[i] = sb + so + ch * 16;
    }
    auto load_stage = [&](int kc, int stage){
        size_t koff = (size_t)kc * BK;
        uint32_t soff = stage * STAGE_B;
        #pragma unroll
        for (int i = 0; i < 6; i++)
            cp_async16(sptr[i] + soff, gptr[i] + koff);
    };

    constexpr int NK = KTOT / BK;
    load_stage(0, 0); cp_commit();
    load_stage(1, 1); cp_commit();

    float    accF[4][4][4];
    uint32_t accH[4][4][2];
    #pragma unroll
    for (int mt = 0; mt < 4; mt++)
        #pragma unroll
        for (int nt = 0; nt < 4; nt++){
            #pragma unroll
            for (int c = 0; c < 4; c++) accF[mt][nt][c] = 0.f;
            accH[mt][nt][0] = 0u; accH[mt][nt][1] = 0u;
        }

    uint32_t aoff = (uint32_t)((warpM * 64 + (lane & 7) + ((lane >> 3) & 1) * 8) * ROW_B
                    + ((lane >> 4) & 1) * 16);
    uint32_t boff = (uint32_t)((warpN * 32 + (lane & 7)) * ROW_B + ((lane >> 3) & 1) * 16);

    int cur = 0, lds = 2;
    #pragma unroll 1
    for (int kc = 0; kc < NK; kc++){
        cp_wait<NSTAGE - 2>();
        __syncthreads();
        int nx = kc + NSTAGE - 1;
        if (nx < NK) load_stage(nx, lds);
        cp_commit();

        uint32_t st = sb + cur * STAGE_B;
        uint32_t aH = st + OFF_AH + aoff, aL = st + OFF_AL + aoff;
        uint32_t bH = st + OFF_BH + boff;
        #pragma unroll
        for (int ks = 0; ks < 2; ks++){
            uint32_t bh[4][2];
            #pragma unroll
            for (int nt = 0; nt < 4; nt++)
                ldmx2(bh[nt], bH + nt * 8 * ROW_B + ks * 32);
            #pragma unroll
            for (int mt = 0; mt < 4; mt++){
                uint32_t ah[4], al[4];
                ldmx4(ah, aH + mt * 16 * ROW_B + ks * 32);
                ldmx4(al, aL + mt * 16 * ROW_B + ks * 32);
                #pragma unroll
                for (int nt = 0; nt < 4; nt++)
                    mma_f32(accF[mt][nt], ah, bh[nt]);     // main: f32 accum
                #pragma unroll
                for (int nt = 0; nt < 4; nt++)
                    mma_f16(accH[mt][nt], al, bh[nt]);     // corr: f16 accum
            }
        }
        cur = (cur == NSTAGE - 1) ? 0 : cur + 1;
        lds = (lds == NSTAGE - 1) ? 0 : lds + 1;
    }

    // epilogue: final = accF + accH * 2^-11 (+bias, relu/split or combine-scatter)
    int rloc  = warpM * 64 + (lane >> 2);
    int cbase = n0 + warpN * 32 + 2 * (lane & 3);
    const float* bptr = bias + (size_t)e * NTOT;
    #pragma unroll
    for (int mt = 0; mt < 4; mt++){
        #pragma unroll
        for (int h = 0; h < 2; h++){
            int slot = m0 + rloc + mt * 16 + h * 8;
            int t = 0; float p = 0.f; float* op = nullptr;
            if constexpr (!G1){
                t = g_slot2tok[e * CAP + slot];
                if (t < 0) continue;
                p = g_slot_prob[e * CAP + slot];
                op = out + (size_t)t * D_MODEL;
            }
            size_t row = (size_t)e * CAP + slot;
            #pragma unroll
            for (int nt = 0; nt < 4; nt++){
                int n = cbase + nt * 8;
                __half2 hc = *reinterpret_cast<__half2*>(&accH[mt][nt][h]);
                float v0 = accF[mt][nt][h*2+0] + __low2float(hc)  * INV_LO + __ldg(bptr + n);
                float v1 = accF[mt][nt][h*2+1] + __high2float(hc) * INV_LO + __ldg(bptr + n + 1);
                if constexpr (G1){
                    v0 = fmaxf(v0, 0.f); v1 = fmaxf(v1, 0.f);
                    unsigned H, L;
                    split2(v0, v1, H, L);
                    *(unsigned*)(g_h_hi + row * DFF + n) = H;
                    *(unsigned*)(g_h_lo + row * DFF + n) = L;
                } else {
                    float2 v = make_float2(v0 * p, v1 * p);
                    *(float2*)(op + n) = v;
                }
            }
        }
    }
}

// ---------------- 6) zero-fill dropped tokens ----------------
__global__ void moe_zero_dropped(float* __restrict__ out){
    int t = blockIdx.x;
    if (g_pos[t] >= 0) return;
    float4* o = (float4*)(out + (size_t)t * D_MODEL);
    for (int i = threadIdx.x; i < D_MODEL / 4; i += blockDim.x)
        o[i] = make_float4(0.f, 0.f, 0.f, 0.f);
}

// ---------------- launch ----------------
extern "C" void kernel_launch(void* const* d_in, const int* in_sizes, int n_in,
                              void* d_out, int out_size){
    const float* inputs = (const float*)d_in[0];
    const float* gate_w = (const float*)d_in[1];
    const float* w1     = (const float*)d_in[2];
    const float* b1     = (const float*)d_in[3];
    const float* w2     = (const float*)d_in[4];
    const float* b2     = (const float*)d_in[5];
    float* out = (float*)d_out;

    cudaFuncSetAttribute(moe_gemm<true>,  cudaFuncAttributeMaxDynamicSharedMemorySize, GEMM_SMEM);
    cudaFuncSetAttribute(moe_gemm<false>, cudaFuncAttributeMaxDynamicSharedMemorySize, GEMM_SMEM);

    moe_gate<<<128, 256>>>(inputs, gate_w);
    moe_scan<<<1, 1024>>>();
    moe_slot_init<<<(N_EXP * CAP + 255) / 256, 256>>>();
    moe_gather<<<T_TOK, 128>>>(inputs);
    moe_tw<true ><<<dim3(DFF / 32,     D_MODEL / 32, N_EXP), dim3(32, 8)>>>(w1);
    moe_tw<false><<<dim3(D_MODEL / 32, DFF / 32,     N_EXP), dim3(32, 8)>>>(w2);
    moe_gemm<true ><<<dim3(DFF / BN,     CAP / BM, N_EXP), 256, GEMM_SMEM>>>(b1, nullptr);
    moe_gemm<false><<<dim3(D_MODEL / BN, CAP / BM, N_EXP), 256, GEMM_SMEM>>>(b2, out);
    moe_zero_dropped<<<T_TOK, 128>>>(out);
}

// round 11
// speedup vs baseline: 3.8303x; 1.5256x over previous
#include <cuda_runtime.h>
#include <cuda_fp16.h>
#include <cstdint>
#include <math.h>

// ---------------- problem constants ----------------
constexpr int T_TOK  = 8192;    // B*S
constexpr int D_MODEL = 1024;
constexpr int N_EXP  = 8;
constexpr int DFF    = 4096;
constexpr int CAP    = 1280;    // ceil(1.25*8192/8)

// ---------------- scratch (__device__ globals; alloc-free rule) ----------------
__device__ float  g_prob[T_TOK];
__device__ int    g_expert[T_TOK];
__device__ int    g_pos[T_TOK];
__device__ int    g_cnt[N_EXP];
__device__ int    g_slot2tok[N_EXP * CAP];
__device__ float  g_slot_prob[N_EXP * CAP];
__device__ __half g_disp[(size_t)N_EXP*CAP*D_MODEL];
__device__ __half g_w1[(size_t)N_EXP*DFF*D_MODEL];   // [e][dff][d]  K-major
__device__ __half g_w2[(size_t)N_EXP*D_MODEL*DFF];   // [e][d][dff]  K-major
__device__ __half g_h[(size_t)N_EXP*CAP*DFF];

// ---------------- helpers ----------------
static __device__ __forceinline__ uint32_t smem_u32(const void* p){
    uint32_t a;
    asm("{ .reg .u64 t; cvta.to.shared.u64 t, %1; cvt.u32.u64 %0, t; }" : "=r"(a) : "l"(p));
    return a;
}
static __device__ __forceinline__ void cp_async16(uint32_t s, const void* g){
    asm volatile("cp.async.cg.shared.global [%0], [%1], 16;" :: "r"(s), "l"(g) : "memory");
}
static __device__ __forceinline__ void cp_commit(){
    asm volatile("cp.async.commit_group;" ::: "memory");
}
template<int N>
static __device__ __forceinline__ void cp_wait(){
    asm volatile("cp.async.wait_group %0;" :: "n"(N) : "memory");
}
static __device__ __forceinline__ void ldmx4(uint32_t* r, uint32_t addr){
    asm volatile("ldmatrix.sync.aligned.m8n8.x4.shared.b16 {%0,%1,%2,%3}, [%4];"
                 : "=r"(r[0]), "=r"(r[1]), "=r"(r[2]), "=r"(r[3]) : "r"(addr));
}
static __device__ __forceinline__ void ldmx2(uint32_t* r, uint32_t addr){
    asm volatile("ldmatrix.sync.aligned.m8n8.x2.shared.b16 {%0,%1}, [%2];"
                 : "=r"(r[0]), "=r"(r[1]) : "r"(addr));
}
// fp16 operands, fp32 accumulator
static __device__ __forceinline__ void mma_f32(float* c, const uint32_t* a, const uint32_t* b){
    asm volatile(
        "mma.sync.aligned.m16n8k16.row.col.f32.f16.f16.f32 "
        "{%0,%1,%2,%3}, {%4,%5,%6,%7}, {%8,%9}, {%0,%1,%2,%3};"
        : "+f"(c[0]), "+f"(c[1]), "+f"(c[2]), "+f"(c[3])
        : "r"(a[0]), "r"(a[1]), "r"(a[2]), "r"(a[3]), "r"(b[0]), "r"(b[1]));
}

// ---------------- 1) gate: fp64-accum logits, softmax top-1 ----------------
__global__ void moe_gate(const float* __restrict__ tokens, const float* __restrict__ gw){
    __shared__ float s_gw[N_EXP * D_MODEL];  // 32 KB
    for (int i = threadIdx.x; i < N_EXP * D_MODEL; i += blockDim.x) s_gw[i] = gw[i];
    __syncthreads();
    int lane  = threadIdx.x & 31;
    int warp  = (blockIdx.x * blockDim.x + threadIdx.x) >> 5;
    int nwarp = (gridDim.x * blockDim.x) >> 5;
    for (int t = warp; t < T_TOK; t += nwarp){
        const float* tok = tokens + (size_t)t * D_MODEL;
        double acc[N_EXP];
        #pragma unroll
        for (int e = 0; e < N_EXP; e++) acc[e] = 0.0;
        for (int d = lane; d < D_MODEL; d += 32){
            double x = (double)tok[d];
            #pragma unroll
            for (int e = 0; e < N_EXP; e++) acc[e] += x * (double)s_gw[e * D_MODEL + d];
        }
        #pragma unroll
        for (int e = 0; e < N_EXP; e++){
            #pragma unroll
            for (int o = 16; o > 0; o >>= 1)
                acc[e] += __shfl_down_sync(0xffffffffu, acc[e], o);
        }
        if (lane == 0){
            int best = 0; double bv = acc[0];
            #pragma unroll
            for (int e = 1; e < N_EXP; e++) if (acc[e] > bv){ bv = acc[e]; best = e; }
            double s = 0.0;
            #pragma unroll
            for (int e = 0; e < N_EXP; e++) s += exp(acc[e] - bv);
            g_prob[t]   = (float)(1.0 / s);
            g_expert[t] = best;
        }
    }
}

// ---------------- 2) order-preserving per-expert rank scan (capacity) ----------------
__global__ void moe_scan(){
    __shared__ int s_base[N_EXP];
    __shared__ int s_wcnt[N_EXP][32];
    int tid = threadIdx.x, lane = tid & 31, w = tid >> 5;
    if (tid < N_EXP) s_base[tid] = 0;
    for (int chunk = 0; chunk < T_TOK / 1024; chunk++){
        if (tid < N_EXP * 32) ((int*)s_wcnt)[tid] = 0;
        __syncthreads();
        int t = chunk * 1024 + tid;
        int e = g_expert[t];
        unsigned m = __match_any_sync(0xffffffffu, e);
        int rw = __popc(m & ((1u << lane) - 1u));
        if (rw == 0) s_wcnt[e][w] = __popc(m);
        __syncthreads();
        int base = s_base[e];
        for (int ww = 0; ww < w; ww++) base += s_wcnt[e][ww];
        int rank = base + rw;
        g_pos[t] = (rank < CAP) ? rank : -1;
        __syncthreads();
        if (tid < N_EXP){
            int s = 0;
            #pragma unroll
            for (int ww = 0; ww < 32; ww++) s += s_wcnt[tid][ww];
            s_base[tid] += s;
        }
        __syncthreads();
    }
    if (tid < N_EXP) g_cnt[tid] = (s_base[tid] < CAP) ? s_base[tid] : CAP;
}

// ---------------- 2b) slot map init ----------------
__global__ void moe_slot_init(){
    int i = blockIdx.x * blockDim.x + threadIdx.x;
    if (i < N_EXP * CAP) g_slot2tok[i] = -1;
}

// ---------------- 3) gather tokens -> dispatch (fp16) + slot maps ----------------
__global__ void moe_gather(const float* __restrict__ tokens){
    int t = blockIdx.x;
    int pos = g_pos[t];
    if (pos < 0) return;
    int e = g_expert[t];
    if (threadIdx.x == 0){
        g_slot2tok[e * CAP + pos]  = t;
        g_slot_prob[e * CAP + pos] = g_prob[t];
    }
    size_t dst = ((size_t)e * CAP + pos) * D_MODEL;
    const float4* src = (const float4*)(tokens + (size_t)t * D_MODEL);
    uint2* dh = (uint2*)(g_disp + dst);
    for (int i = threadIdx.x; i < D_MODEL / 4; i += blockDim.x){
        float4 v = src[i];
        __half2 h0 = __floats2half2_rn(v.x, v.y);
        __half2 h1 = __floats2half2_rn(v.z, v.w);
        uint2 H;
        H.x = *reinterpret_cast<unsigned*>(&h0);
        H.y = *reinterpret_cast<unsigned*>(&h1);
        dh[i] = H;
    }
}

// ---------------- 4) weight transpose (to K-major fp16) ----------------
template<bool W1>
__global__ void moe_tw(const float* __restrict__ w){
    constexpr int R = W1 ? D_MODEL : DFF;   // rows of w  (= K of gemm)
    constexpr int C = W1 ? DFF : D_MODEL;   // cols of w  (= N of gemm)
    __half* oh = W1 ? g_w1 : g_w2;
    __shared__ float tile[32][33];
    int e = blockIdx.z;
    int c0 = blockIdx.x * 32, r0 = blockIdx.y * 32;
    const float* wp = w + (size_t)e * R * C;
    int x = threadIdx.x, y0 = threadIdx.y;    // blockDim (32, 8)
    #pragma unroll
    for (int yy = 0; yy < 32; yy += 8)
        tile[y0 + yy][x] = wp[(size_t)(r0 + y0 + yy) * C + c0 + x];
    __syncthreads();
    __half* poh = oh + (size_t)e * R * C;
    #pragma unroll
    for (int yy = 0; yy < 32; yy += 8){
        float v = tile[x][y0 + yy];
        size_t o = (size_t)(c0 + y0 + yy) * R + r0 + x;
        poh[o] = __float2half_rn(v);
    }
}

// ---------------- 5) HMMA fp16 GEMM: BM=128 BN=128 BK=32, 4-stage cp.async ----------------
constexpr int BM = 128, BN = 128, BK = 32;
constexpr int ROW_B   = 80;                      // padded row stride (64B data + 16B pad)
constexpr int OFF_A   = 0;
constexpr int OFF_B   = 128 * ROW_B;
constexpr int STAGE_B = 256 * ROW_B;             // 20480
constexpr int NSTAGE  = 4;
constexpr int GEMM_SMEM = NSTAGE * STAGE_B;      // 81920

template<bool G1>
__global__ void __launch_bounds__(256, 2) moe_gemm(const float* __restrict__ bias,
                                                   float* __restrict__ out){
    constexpr int KTOT = G1 ? D_MODEL : DFF;
    constexpr int NTOT = G1 ? DFF : D_MODEL;
    const __half* A = G1 ? g_disp : g_h;
    const __half* B = G1 ? g_w1 : g_w2;

    int e = blockIdx.z, m0 = blockIdx.y * BM, n0 = blockIdx.x * BN;
    int cnt = g_cnt[e];
    if (m0 >= cnt) return;          // expert has no tokens in this m-tile

    extern __shared__ char smem[];
    uint32_t sb = smem_u32(smem);

    int tid  = threadIdx.x;
    int lane = tid & 31;
    int wid  = tid >> 5;
    int warpM = wid & 1;            // 2 x 4 warp grid; warp tile 64x32
    int warpN = wid >> 1;

    const __half* baseA = A + ((size_t)e * CAP  + m0) * KTOT;
    const __half* baseB = B + ((size_t)e * NTOT + n0) * KTOT;

    // per-thread cp.async slots: idx = tid + i*256 (i<4); row = idx>>2 (0..255), ch = idx&3
    const __half* gptr[4];
    uint32_t sptr[4];
    #pragma unroll
    for (int i = 0; i < 4; i++){
        int idx = tid + i * 256;
        int row = idx >> 2, ch = idx & 3;
        const __half* gb; uint32_t so;
        if (row < 128) { gb = baseA + (size_t)row * KTOT;        so = OFF_A + row * ROW_B; }
        else           { gb = baseB + (size_t)(row-128) * KTOT;  so = OFF_B + (row-128) * ROW_B; }
        gptr[i] = gb + ch * 8;
        sptr[i] = sb + so + ch * 16;
    }
    auto load_stage = [&](int kc, int stage){
        size_t koff = (size_t)kc * BK;
        uint32_t soff = stage * STAGE_B;
        #pragma unroll
        for (int i = 0; i < 4; i++)
            cp_async16(sptr[i] + soff, gptr[i] + koff);
    };

    constexpr int NK = KTOT / BK;
    #pragma unroll
    for (int s = 0; s < NSTAGE - 1; s++){ load_stage(s, s); cp_commit(); }

    float accF[4][4][4];
    #pragma unroll
    for (int mt = 0; mt < 4; mt++)
        #pragma unroll
        for (int nt = 0; nt < 4; nt++)
            #pragma unroll
            for (int c = 0; c < 4; c++) accF[mt][nt][c] = 0.f;

    uint32_t aoff = (uint32_t)((warpM * 64 + (lane & 7) + ((lane >> 3) & 1) * 8) * ROW_B
                    + ((lane >> 4) & 1) * 16);
    uint32_t boff = (uint32_t)((warpN * 32 + (lane & 7)) * ROW_B + ((lane >> 3) & 1) * 16);

    int cur = 0, lds = NSTAGE - 1;
    #pragma unroll 1
    for (int kc = 0; kc < NK; kc++){
        cp_wait<NSTAGE - 2>();
        __syncthreads();
        int nx = kc + NSTAGE - 1;
        if (nx < NK) load_stage(nx, lds);
        cp_commit();

        uint32_t st = sb + cur * STAGE_B;
        uint32_t aH = st + OFF_A + aoff;
        uint32_t bH = st + OFF_B + boff;
        #pragma unroll
        for (int ks = 0; ks < 2; ks++){
            uint32_t bh[4][2];
            #pragma unroll
            for (int nt = 0; nt < 4; nt++)
                ldmx2(bh[nt], bH + nt * 8 * ROW_B + ks * 32);
            #pragma unroll
            for (int mt = 0; mt < 4; mt++){
                uint32_t ah[4];
                ldmx4(ah, aH + mt * 16 * ROW_B + ks * 32);
                #pragma unroll
                for (int nt = 0; nt < 4; nt++)
                    mma_f32(accF[mt][nt], ah, bh[nt]);
            }
        }
        cur = (cur == NSTAGE - 1) ? 0 : cur + 1;
        lds = (lds == NSTAGE - 1) ? 0 : lds + 1;
    }

    // epilogue
    int rloc  = warpM * 64 + (lane >> 2);
    int cbase = n0 + warpN * 32 + 2 * (lane & 3);
    const float* bptr = bias + (size_t)e * NTOT;
    #pragma unroll
    for (int mt = 0; mt < 4; mt++){
        #pragma unroll
        for (int h = 0; h < 2; h++){
            int slot = m0 + rloc + mt * 16 + h * 8;
            int t = 0; float p = 0.f; float* op = nullptr;
            if constexpr (!G1){
                t = g_slot2tok[e * CAP + slot];
                if (t < 0) continue;
                p = g_slot_prob[e * CAP + slot];
                op = out + (size_t)t * D_MODEL;
            }
            size_t row = (size_t)e * CAP + slot;
            #pragma unroll
            for (int nt = 0; nt < 4; nt++){
                int n = cbase + nt * 8;
                float v0 = accF[mt][nt][h*2+0] + __ldg(bptr + n);
                float v1 = accF[mt][nt][h*2+1] + __ldg(bptr + n + 1);
                if constexpr (G1){
                    v0 = fmaxf(v0, 0.f); v1 = fmaxf(v1, 0.f);
                    __half2 hv = __floats2half2_rn(v0, v1);
                    *(unsigned*)(g_h + row * DFF + n) = *reinterpret_cast<unsigned*>(&hv);
                } else {
                    float2 v = make_float2(v0 * p, v1 * p);
                    *(float2*)(op + n) = v;
                }
            }
        }
    }
}

// ---------------- 6) zero-fill dropped tokens ----------------
__global__ void moe_zero_dropped(float* __restrict__ out){
    int t = blockIdx.x;
    if (g_pos[t] >= 0) return;
    float4* o = (float4*)(out + (size_t)t * D_MODEL);
    for (int i = threadIdx.x; i < D_MODEL / 4; i += blockDim.x)
        o[i] = make_float4(0.f, 0.f, 0.f, 0.f);
}

// ---------------- launch ----------------
extern "C" void kernel_launch(void* const* d_in, const int* in_sizes, int n_in,
                              void* d_out, int out_size){
    const float* inputs = (const float*)d_in[0];
    const float* gate_w = (const float*)d_in[1];
    const float* w1     = (const float*)d_in[2];
    const float* b1     = (const float*)d_in[3];
    const float* w2     = (const float*)d_in[4];
    const float* b2     = (const float*)d_in[5];
    float* out = (float*)d_out;

    cudaFuncSetAttribute(moe_gemm<true>,  cudaFuncAttributeMaxDynamicSharedMemorySize, GEMM_SMEM);
    cudaFuncSetAttribute(moe_gemm<false>, cudaFuncAttributeMaxDynamicSharedMemorySize, GEMM_SMEM);

    moe_gate<<<128, 256>>>(inputs, gate_w);
    moe_scan<<<1, 1024>>>();
    moe_slot_init<<<(N_EXP * CAP + 255) / 256, 256>>>();
    moe_gather<<<T_TOK, 128>>>(inputs);
    moe_tw<true ><<<dim3(DFF / 32,     D_MODEL / 32, N_EXP), dim3(32, 8)>>>(w1);
    moe_tw<false><<<dim3(D_MODEL / 32, DFF / 32,     N_EXP), dim3(32, 8)>>>(w2);
    moe_gemm<true ><<<dim3(DFF / BN,     CAP / BM, N_EXP), 256, GEMM_SMEM>>>(b1, nullptr);
    moe_gemm<false><<<dim3(D_MODEL / BN, CAP / BM, N_EXP), 256, GEMM_SMEM>>>(b2, out);
    moe_zero_dropped<<<T_TOK, 128>>>(out);
}